// round 1
// baseline (speedup 1.0000x reference)
#include <cuda_runtime.h>
#include <math.h>

#define SEQ 8192
#define HID 1024
#define NCHUNK 32            // row chunks for column-softmax partials (8192/32 = 256 rows each)
#define ROWS_PER_CHUNK (SEQ / NCHUNK)

// ---- device scratch (static allocation; no runtime mallocs allowed) ----
__device__ float g_q[(size_t)SEQ * HID];
__device__ float g_k[(size_t)SEQ * HID];
__device__ float g_sc[(size_t)SEQ * SEQ];      // 268 MB scores scratch
__device__ float g_pm[NCHUNK * SEQ];           // partial col max
__device__ float g_ps[NCHUNK * SEQ];           // partial col sumexp
__device__ float g_cm[SEQ];                    // final col max
__device__ float g_cz[SEQ];                    // 1 / col sumexp

// ============================================================================
// NT SGEMM: C[M,N] = A[M,K] * B[N,K]^T, all row-major, fp32.
// 128x128 block tile, BK=16, 256 threads, 8x8 per thread.
// Dims assumed divisible (8192,1024 by 128/16) -> no bounds checks.
// ============================================================================
template <int APPLY_TANH>
__global__ __launch_bounds__(256, 2)
void gemm_nt_kernel(const float* __restrict__ A, const float* __restrict__ B,
                    float* __restrict__ C, int M, int N, int K)
{
    __shared__ float As[16][128];
    __shared__ float Bs[16][128];

    const int tid = threadIdx.x;
    const int tx  = tid & 15;          // 0..15  -> 8 cols each
    const int ty  = tid >> 4;          // 0..15  -> 8 rows each
    const int lr  = tid >> 2;          // 0..63  load row
    const int lc  = (tid & 3) << 2;    // 0,4,8,12 load k-offset

    const float* Ag = A + (size_t)blockIdx.y * 128 * K;
    const float* Bg = B + (size_t)blockIdx.x * 128 * K;

    float acc[8][8];
#pragma unroll
    for (int i = 0; i < 8; i++)
#pragma unroll
        for (int j = 0; j < 8; j++) acc[i][j] = 0.f;

    for (int k0 = 0; k0 < K; k0 += 16) {
#pragma unroll
        for (int r = 0; r < 2; r++) {
            const int row = lr + r * 64;
            float4 va = *(const float4*)(Ag + (size_t)row * K + (k0 + lc));
            As[lc + 0][row] = va.x; As[lc + 1][row] = va.y;
            As[lc + 2][row] = va.z; As[lc + 3][row] = va.w;
            float4 vb = *(const float4*)(Bg + (size_t)row * K + (k0 + lc));
            Bs[lc + 0][row] = vb.x; Bs[lc + 1][row] = vb.y;
            Bs[lc + 2][row] = vb.z; Bs[lc + 3][row] = vb.w;
        }
        __syncthreads();

#pragma unroll
        for (int kk = 0; kk < 16; kk++) {
            float4 a0 = *(const float4*)&As[kk][ty * 8];
            float4 a1 = *(const float4*)&As[kk][ty * 8 + 4];
            float4 b0 = *(const float4*)&Bs[kk][tx * 8];
            float4 b1 = *(const float4*)&Bs[kk][tx * 8 + 4];
            float a[8] = {a0.x, a0.y, a0.z, a0.w, a1.x, a1.y, a1.z, a1.w};
            float b[8] = {b0.x, b0.y, b0.z, b0.w, b1.x, b1.y, b1.z, b1.w};
#pragma unroll
            for (int i = 0; i < 8; i++)
#pragma unroll
                for (int j = 0; j < 8; j++)
                    acc[i][j] = fmaf(a[i], b[j], acc[i][j]);
        }
        __syncthreads();
    }

    const int crow0 = blockIdx.y * 128 + ty * 8;
    const int ccol0 = blockIdx.x * 128 + tx * 8;
#pragma unroll
    for (int i = 0; i < 8; i++) {
        float* Cp = C + (size_t)(crow0 + i) * N + ccol0;
#pragma unroll
        for (int j = 0; j < 8; j += 4) {
            float4 v;
            v.x = acc[i][j];     v.y = acc[i][j + 1];
            v.z = acc[i][j + 2]; v.w = acc[i][j + 3];
            if (APPLY_TANH) {
                v.x = tanhf(v.x); v.y = tanhf(v.y);
                v.z = tanhf(v.z); v.w = tanhf(v.w);
            }
            *(float4*)(Cp + j) = v;
        }
    }
}

// ============================================================================
// Column softmax (softmax over row index i for each column j).
// Pass 1: per-(column, row-chunk) online (max, sumexp) partials.
// Coalesced: consecutive threads = consecutive columns j.
// ============================================================================
__global__ void softmax_col_partial(const float* __restrict__ Sc)
{
    const int j     = blockIdx.x * blockDim.x + threadIdx.x;   // column
    const int chunk = blockIdx.y;
    const float* p  = Sc + (size_t)chunk * ROWS_PER_CHUNK * SEQ + j;

    float m = -3.402823e38f, s = 0.f;
#pragma unroll 8
    for (int i = 0; i < ROWS_PER_CHUNK; i++) {
        float x  = p[(size_t)i * SEQ];
        float mn = fmaxf(m, x);
        s = s * __expf(m - mn) + __expf(x - mn);
        m = mn;
    }
    g_pm[chunk * SEQ + j] = m;
    g_ps[chunk * SEQ + j] = s;
}

// Pass 2: merge the NCHUNK partials per column.
__global__ void softmax_col_merge()
{
    const int j = blockIdx.x * blockDim.x + threadIdx.x;
    float m = -3.402823e38f;
#pragma unroll
    for (int c = 0; c < NCHUNK; c++) m = fmaxf(m, g_pm[c * SEQ + j]);
    float z = 0.f;
#pragma unroll
    for (int c = 0; c < NCHUNK; c++) z += g_ps[c * SEQ + j] * __expf(g_pm[c * SEQ + j] - m);
    g_cm[j] = m;
    g_cz[j] = 1.0f / z;
}

// Pass 3: attn[i,j] = exp(sc[i,j] - m[j]) / Z[j], vectorized float4.
__global__ void softmax_normalize(const float* __restrict__ Sc, float* __restrict__ attn)
{
    const size_t t   = (size_t)blockIdx.x * blockDim.x + threadIdx.x;
    const size_t idx = t * 4;
    const int j = (int)(idx & (SEQ - 1));

    float4 x = *(const float4*)(Sc + idx);
    float4 m = *(const float4*)(g_cm + j);
    float4 z = *(const float4*)(g_cz + j);
    float4 o;
    o.x = __expf(x.x - m.x) * z.x;
    o.y = __expf(x.y - m.y) * z.y;
    o.z = __expf(x.z - m.z) * z.z;
    o.w = __expf(x.w - m.w) * z.w;
    *(float4*)(attn + idx) = o;
}

// context = col_sum(attn) * enc_out, and col_sum of a softmax over that axis == 1,
// so context is exactly enc_out (matches reference to ~1e-7 rel).
__global__ void copy_context(const float* __restrict__ enc, float* __restrict__ ctx)
{
    const size_t t = (size_t)blockIdx.x * blockDim.x + threadIdx.x;
    ((float4*)ctx)[t] = ((const float4*)enc)[t];
}

// ============================================================================
extern "C" void kernel_launch(void* const* d_in, const int* in_sizes, int n_in,
                              void* d_out, int out_size)
{
    const float* enc = (const float*)d_in[0];
    const float* w1  = (const float*)d_in[1];
    const float* w2  = (const float*)d_in[2];
    float* out  = (float*)d_out;
    float* ctx  = out;                          // [1, S, H]
    float* attn = out + (size_t)SEQ * HID;      // [1, S, S]

    float *q, *k, *sc;
    cudaGetSymbolAddress((void**)&q,  g_q);
    cudaGetSymbolAddress((void**)&k,  g_k);
    cudaGetSymbolAddress((void**)&sc, g_sc);

    // q = tanh(enc @ w1^T), k = enc @ w2^T
    gemm_nt_kernel<1><<<dim3(HID / 128, SEQ / 128), 256>>>(enc, w1, q, SEQ, HID, HID);
    gemm_nt_kernel<0><<<dim3(HID / 128, SEQ / 128), 256>>>(enc, w2, k, SEQ, HID, HID);

    // scores = q @ k^T  [S, S]
    gemm_nt_kernel<0><<<dim3(SEQ / 128, SEQ / 128), 256>>>(q, k, sc, SEQ, SEQ, HID);

    // column softmax (over axis i)
    softmax_col_partial<<<dim3(SEQ / 256, NCHUNK), 256>>>(sc);
    softmax_col_merge<<<SEQ / 256, 256>>>();
    softmax_normalize<<<((size_t)SEQ * SEQ / 4) / 256, 256>>>(sc, attn);

    // context = enc_out (softmax column sums are exactly 1)
    copy_context<<<((size_t)SEQ * HID / 4) / 256, 256>>>(enc, ctx);
}

// round 4
// speedup vs baseline: 2.9991x; 2.9991x over previous
#include <cuda_runtime.h>
#include <cuda_bf16.h>
#include <math.h>
#include <cstdint>

#define SEQ 8192
#define HID 1024
#define NCHUNK 32
#define ROWS_PER_CHUNK (SEQ / NCHUNK)

// ---------------- device scratch (static; no runtime alloc) ----------------
__device__ __nv_bfloat16 g_ehi[(size_t)SEQ * HID];
__device__ __nv_bfloat16 g_elo[(size_t)SEQ * HID];
__device__ __nv_bfloat16 g_w1hi[HID * HID], g_w1lo[HID * HID];
__device__ __nv_bfloat16 g_w2hi[HID * HID], g_w2lo[HID * HID];
__device__ __nv_bfloat16 g_qhi[(size_t)SEQ * HID], g_qlo[(size_t)SEQ * HID];
__device__ __nv_bfloat16 g_khi[(size_t)SEQ * HID], g_klo[(size_t)SEQ * HID];
__device__ float g_sc[(size_t)SEQ * SEQ];
__device__ float g_pm[NCHUNK * SEQ];
__device__ float g_ps[NCHUNK * SEQ];
__device__ float g_cm[SEQ];
__device__ float g_cz[SEQ];

// ---------------- helpers ----------------
__device__ __forceinline__ uint32_t smem_u32(const void* p) {
    uint32_t a;
    asm("{ .reg .u64 t; cvta.to.shared.u64 t, %1; cvt.u32.u64 %0, t; }" : "=r"(a) : "l"(p));
    return a;
}
#define SWZ(off) ((off) ^ (((off) >> 3) & 0x70))
#define CP_ASYNC16(dst, src) \
    asm volatile("cp.async.cg.shared.global [%0], [%1], 16;" :: "r"(dst), "l"(src) : "memory")
#define CP_COMMIT() asm volatile("cp.async.commit_group;" ::: "memory")
#define CP_WAIT(n)  asm volatile("cp.async.wait_group %0;" :: "n"(n) : "memory")

__device__ __forceinline__ void ldsm4(uint32_t& r0, uint32_t& r1, uint32_t& r2, uint32_t& r3,
                                      uint32_t addr) {
    asm volatile("ldmatrix.sync.aligned.m8n8.x4.shared.b16 {%0,%1,%2,%3}, [%4];"
                 : "=r"(r0), "=r"(r1), "=r"(r2), "=r"(r3) : "r"(addr));
}
__device__ __forceinline__ void mma_bf16(float* c, const uint32_t* a, uint32_t b0, uint32_t b1) {
    asm volatile("mma.sync.aligned.m16n8k16.row.col.f32.bf16.bf16.f32 "
                 "{%0,%1,%2,%3}, {%4,%5,%6,%7}, {%8,%9}, {%0,%1,%2,%3};"
                 : "+f"(c[0]), "+f"(c[1]), "+f"(c[2]), "+f"(c[3])
                 : "r"(a[0]), "r"(a[1]), "r"(a[2]), "r"(a[3]), "r"(b0), "r"(b1));
}

// ---------------- GEMM geometry ----------------
// CTA tile M=256, N=128, K-chunk 64 (128B rows). 256 threads = 8 warps (4m x 2n),
// warp tile 64x64. 2-stage cp.async pipeline. NT layout: C = A[M,K] * B[N,K]^T.
#define AH_OFF 0
#define AL_OFF 32768
#define BH_OFF 65536
#define BL_OFF 81920
#define STAGE  98304
#define SMEM_TOT (2 * STAGE)   // 192 KB

// MODE 0: fp32 C.  MODE 1: tanh + bf16 hi/lo split.  MODE 2: bf16 hi/lo split.
template <int MODE>
__global__ __launch_bounds__(256, 1)
void gemm3_mma(const __nv_bfloat16* __restrict__ Ahi, const __nv_bfloat16* __restrict__ Alo,
               const __nv_bfloat16* __restrict__ Bhi, const __nv_bfloat16* __restrict__ Blo,
               float* __restrict__ Cf, __nv_bfloat16* __restrict__ Chi,
               __nv_bfloat16* __restrict__ Clo, int Ncols, int K)
{
    extern __shared__ char smem[];
    const uint32_t sb = smem_u32(smem);
    const int tid = threadIdx.x;
    const int l = tid & 31, w = tid >> 5;
    const int wm = w & 3, wn = w >> 2;         // 4 x 2 warp grid
    const int m0 = blockIdx.y * 256;
    const int n0 = blockIdx.x * 128;
    const int NS = K >> 6;

    float acc[4][8][4];
#pragma unroll
    for (int a = 0; a < 4; a++)
#pragma unroll
        for (int b = 0; b < 8; b++)
#pragma unroll
            for (int c = 0; c < 4; c++) acc[a][b][c] = 0.f;

    // ---- async stage loader: 768 rows x 128B = 6144 x 16B chunks, 24/thread ----
    auto issue = [&](int s) {
        const int k0 = s << 6;
        const uint32_t st = sb + (uint32_t)(s & 1) * STAGE;
#pragma unroll
        for (int i = 0; i < 24; ++i) {
            const int cid = tid + i * 256;
            const int row = cid >> 3, ch = cid & 7;
            const __nv_bfloat16* g;
            uint32_t off;
            int r;
            if (row < 256)      { r = row;       g = Ahi + (size_t)(m0 + r) * K; off = AH_OFF; }
            else if (row < 512) { r = row - 256; g = Alo + (size_t)(m0 + r) * K; off = AL_OFF; }
            else if (row < 640) { r = row - 512; g = Bhi + (size_t)(n0 + r) * K; off = BH_OFF; }
            else                { r = row - 640; g = Blo + (size_t)(n0 + r) * K; off = BL_OFF; }
            CP_ASYNC16(st + off + SWZ(r * 128 + ch * 16), g + k0 + ch * 8);
        }
        CP_COMMIT();
    };

    issue(0);

    // ldmatrix lane address components
    const int arow = ((l >> 3) & 1) * 8 + (l & 7);   // A: mat0 m0-7/klo, mat1 m8-15/klo, mat2/3 khi
    const int akh  = l >> 4;
    const int brow = ((l >> 4) & 1) * 8 + (l & 7);   // B: mat0 n0-7/klo, mat1 n0-7/khi, mat2/3 n8-15
    const int bkh  = (l >> 3) & 1;

    for (int s = 0; s < NS; ++s) {
        if (s + 1 < NS) { issue(s + 1); CP_WAIT(1); }
        else            { CP_WAIT(0); }
        __syncthreads();
        const uint32_t st = sb + (uint32_t)(s & 1) * STAGE;

#pragma unroll
        for (int kk = 0; kk < 4; ++kk) {
            const int kb = kk * 32;
            uint32_t A[4][4], Bh[4][4], Bl[4][4];
#pragma unroll
            for (int nt2 = 0; nt2 < 4; ++nt2) {
                const uint32_t boff = SWZ((wn * 64 + nt2 * 16 + brow) * 128 + kb + bkh * 16);
                ldsm4(Bh[nt2][0], Bh[nt2][1], Bh[nt2][2], Bh[nt2][3], st + BH_OFF + boff);
                ldsm4(Bl[nt2][0], Bl[nt2][1], Bl[nt2][2], Bl[nt2][3], st + BL_OFF + boff);
            }
#pragma unroll
            for (int mt = 0; mt < 4; ++mt) {
                const uint32_t aoff = SWZ((wm * 64 + mt * 16 + arow) * 128 + kb + akh * 16);
                ldsm4(A[mt][0], A[mt][1], A[mt][2], A[mt][3], st + AH_OFF + aoff);
            }
            // hi*hi + hi*lo
#pragma unroll
            for (int mt = 0; mt < 4; ++mt)
#pragma unroll
                for (int nt2 = 0; nt2 < 4; ++nt2) {
                    mma_bf16(acc[mt][nt2 * 2 + 0], A[mt], Bh[nt2][0], Bh[nt2][1]);
                    mma_bf16(acc[mt][nt2 * 2 + 1], A[mt], Bh[nt2][2], Bh[nt2][3]);
                    mma_bf16(acc[mt][nt2 * 2 + 0], A[mt], Bl[nt2][0], Bl[nt2][1]);
                    mma_bf16(acc[mt][nt2 * 2 + 1], A[mt], Bl[nt2][2], Bl[nt2][3]);
                }
            // lo*hi (reload A as lo, reuse registers)
#pragma unroll
            for (int mt = 0; mt < 4; ++mt) {
                const uint32_t aoff = SWZ((wm * 64 + mt * 16 + arow) * 128 + kb + akh * 16);
                ldsm4(A[mt][0], A[mt][1], A[mt][2], A[mt][3], st + AL_OFF + aoff);
            }
#pragma unroll
            for (int mt = 0; mt < 4; ++mt)
#pragma unroll
                for (int nt2 = 0; nt2 < 4; ++nt2) {
                    mma_bf16(acc[mt][nt2 * 2 + 0], A[mt], Bh[nt2][0], Bh[nt2][1]);
                    mma_bf16(acc[mt][nt2 * 2 + 1], A[mt], Bh[nt2][2], Bh[nt2][3]);
                }
        }
        __syncthreads();
    }

    // ---- epilogue ----
    const int cr = l >> 2, cc = 2 * (l & 3);
#pragma unroll
    for (int mt = 0; mt < 4; ++mt) {
#pragma unroll
        for (int nt = 0; nt < 8; ++nt) {
            const int row = m0 + wm * 64 + mt * 16 + cr;
            const int col = n0 + wn * 64 + nt * 8 + cc;
            const float* c = acc[mt][nt];
            if (MODE == 0) {
                float2 v0 = make_float2(c[0], c[1]);
                float2 v1 = make_float2(c[2], c[3]);
                *(float2*)(Cf + (size_t)row * Ncols + col) = v0;
                *(float2*)(Cf + (size_t)(row + 8) * Ncols + col) = v1;
            } else {
#pragma unroll
                for (int h = 0; h < 2; ++h) {
                    float f0 = c[2 * h + 0], f1 = c[2 * h + 1];
                    if (MODE == 1) { f0 = tanhf(f0); f1 = tanhf(f1); }
                    __nv_bfloat16 h0 = __float2bfloat16(f0);
                    __nv_bfloat16 h1 = __float2bfloat16(f1);
                    __nv_bfloat16 l0 = __float2bfloat16(f0 - __bfloat162float(h0));
                    __nv_bfloat16 l1 = __float2bfloat16(f1 - __bfloat162float(h1));
                    const size_t o = (size_t)(row + 8 * h) * Ncols + col;
                    *(__nv_bfloat162*)(Chi + o) = __halves2bfloat162(h0, h1);
                    *(__nv_bfloat162*)(Clo + o) = __halves2bfloat162(l0, l1);
                }
            }
        }
    }
}

// ---------------- fp32 -> bf16 hi/lo split ----------------
__global__ void split_kernel(const float* __restrict__ src, __nv_bfloat16* __restrict__ hi,
                             __nv_bfloat16* __restrict__ lo, int n4)
{
    const int t = blockIdx.x * blockDim.x + threadIdx.x;
    if (t >= n4) return;
    float4 v = ((const float4*)src)[t];
    __nv_bfloat16 h0 = __float2bfloat16(v.x), h1 = __float2bfloat16(v.y);
    __nv_bfloat16 h2 = __float2bfloat16(v.z), h3 = __float2bfloat16(v.w);
    __nv_bfloat16 l0 = __float2bfloat16(v.x - __bfloat162float(h0));
    __nv_bfloat16 l1 = __float2bfloat16(v.y - __bfloat162float(h1));
    __nv_bfloat16 l2 = __float2bfloat16(v.z - __bfloat162float(h2));
    __nv_bfloat16 l3 = __float2bfloat16(v.w - __bfloat162float(h3));
    ((__nv_bfloat162*)hi)[2 * t + 0] = __halves2bfloat162(h0, h1);
    ((__nv_bfloat162*)hi)[2 * t + 1] = __halves2bfloat162(h2, h3);
    ((__nv_bfloat162*)lo)[2 * t + 0] = __halves2bfloat162(l0, l1);
    ((__nv_bfloat162*)lo)[2 * t + 1] = __halves2bfloat162(l2, l3);
}

// ---------------- column softmax over axis i ----------------
__global__ void softmax_col_partial(const float* __restrict__ Sc)
{
    const int j     = blockIdx.x * blockDim.x + threadIdx.x;
    const int chunk = blockIdx.y;
    const float* p  = Sc + (size_t)chunk * ROWS_PER_CHUNK * SEQ + j;
    float m = -3.402823e38f, s = 0.f;
#pragma unroll 8
    for (int i = 0; i < ROWS_PER_CHUNK; i++) {
        float x  = p[(size_t)i * SEQ];
        float mn = fmaxf(m, x);
        s = s * __expf(m - mn) + __expf(x - mn);
        m = mn;
    }
    g_pm[chunk * SEQ + j] = m;
    g_ps[chunk * SEQ + j] = s;
}

__global__ void softmax_col_merge()
{
    const int j = blockIdx.x * blockDim.x + threadIdx.x;
    float m = -3.402823e38f;
#pragma unroll
    for (int c = 0; c < NCHUNK; c++) m = fmaxf(m, g_pm[c * SEQ + j]);
    float z = 0.f;
#pragma unroll
    for (int c = 0; c < NCHUNK; c++) z += g_ps[c * SEQ + j] * __expf(g_pm[c * SEQ + j] - m);
    g_cm[j] = m;
    g_cz[j] = 1.0f / z;
}

__global__ void softmax_normalize(const float* __restrict__ Sc, float* __restrict__ attn)
{
    const size_t t   = (size_t)blockIdx.x * blockDim.x + threadIdx.x;
    const size_t idx = t * 4;
    const int j = (int)(idx & (SEQ - 1));
    float4 x = *(const float4*)(Sc + idx);
    float4 m = *(const float4*)(g_cm + j);
    float4 z = *(const float4*)(g_cz + j);
    float4 o;
    o.x = __expf(x.x - m.x) * z.x;
    o.y = __expf(x.y - m.y) * z.y;
    o.z = __expf(x.z - m.z) * z.z;
    o.w = __expf(x.w - m.w) * z.w;
    *(float4*)(attn + idx) = o;
}

// context = col_sum(attn) * enc_out; softmax column sums are exactly 1 -> copy.
__global__ void copy_context(const float* __restrict__ enc, float* __restrict__ ctx)
{
    const size_t t = (size_t)blockIdx.x * blockDim.x + threadIdx.x;
    ((float4*)ctx)[t] = ((const float4*)enc)[t];
}

// ============================================================================
extern "C" void kernel_launch(void* const* d_in, const int* in_sizes, int n_in,
                              void* d_out, int out_size)
{
    const float* enc = (const float*)d_in[0];
    const float* w1  = (const float*)d_in[1];
    const float* w2  = (const float*)d_in[2];
    float* out  = (float*)d_out;
    float* ctx  = out;
    float* attn = out + (size_t)SEQ * HID;

    __nv_bfloat16 *ehi, *elo, *w1hi, *w1lo, *w2hi, *w2lo, *qhi, *qlo, *khi, *klo;
    float* sc;
    cudaGetSymbolAddress((void**)&ehi,  g_ehi);
    cudaGetSymbolAddress((void**)&elo,  g_elo);
    cudaGetSymbolAddress((void**)&w1hi, g_w1hi);
    cudaGetSymbolAddress((void**)&w1lo, g_w1lo);
    cudaGetSymbolAddress((void**)&w2hi, g_w2hi);
    cudaGetSymbolAddress((void**)&w2lo, g_w2lo);
    cudaGetSymbolAddress((void**)&qhi,  g_qhi);
    cudaGetSymbolAddress((void**)&qlo,  g_qlo);
    cudaGetSymbolAddress((void**)&khi,  g_khi);
    cudaGetSymbolAddress((void**)&klo,  g_klo);
    cudaGetSymbolAddress((void**)&sc,   g_sc);

    cudaFuncSetAttribute(gemm3_mma<0>, cudaFuncAttributeMaxDynamicSharedMemorySize, SMEM_TOT);
    cudaFuncSetAttribute(gemm3_mma<1>, cudaFuncAttributeMaxDynamicSharedMemorySize, SMEM_TOT);
    cudaFuncSetAttribute(gemm3_mma<2>, cudaFuncAttributeMaxDynamicSharedMemorySize, SMEM_TOT);

    // 1) split inputs into bf16 hi/lo
    split_kernel<<<(SEQ * HID / 4) / 256, 256>>>(enc, ehi, elo, SEQ * HID / 4);
    split_kernel<<<(HID * HID / 4) / 256, 256>>>(w1, w1hi, w1lo, HID * HID / 4);
    split_kernel<<<(HID * HID / 4) / 256, 256>>>(w2, w2hi, w2lo, HID * HID / 4);

    // 2) q = tanh(enc @ w1^T), k = enc @ w2^T  (bf16 hi/lo outputs)
    gemm3_mma<1><<<dim3(HID / 128, SEQ / 256), 256, SMEM_TOT>>>(
        ehi, elo, w1hi, w1lo, nullptr, qhi, qlo, HID, HID);
    gemm3_mma<2><<<dim3(HID / 128, SEQ / 256), 256, SMEM_TOT>>>(
        ehi, elo, w2hi, w2lo, nullptr, khi, klo, HID, HID);

    // 3) scores = q @ k^T (fp32 out)
    gemm3_mma<0><<<dim3(SEQ / 128, SEQ / 256), 256, SMEM_TOT>>>(
        qhi, qlo, khi, klo, sc, nullptr, nullptr, SEQ, HID);

    // 4) column softmax
    softmax_col_partial<<<dim3(SEQ / 256, NCHUNK), 256>>>(sc);
    softmax_col_merge<<<SEQ / 256, 256>>>();
    softmax_normalize<<<((size_t)SEQ * SEQ / 4) / 256, 256>>>(sc, attn);

    // 5) context = enc_out
    copy_context<<<((size_t)SEQ * HID / 4) / 256, 256>>>(enc, ctx);
}